// round 6
// baseline (speedup 1.0000x reference)
#include <cuda_runtime.h>
#include <math.h>

#define BA 2048          // B*A
#define E  256
#define H  128
#define KF 12
#define NORM 0.08838834764831845f   // 1/sqrt(128)

// Scratch (static __device__ to satisfy no-alloc rule)
__device__ float g_qk [BA * H];              // vs0 @ (Wq @ Wk^T)
__device__ float g_wve[BA * H];              // softmax-weighted sum of ve rows
__device__ float g_veC[(size_t)BA * KF * H]; // gathered top-12 entity rows
__device__ float g_M  [H * H];               // Wq @ Wk^T
__device__ float g_P  [H * H];               // Wv @ W1[H:,:]

// ---------------------------------------------------------------------------
// Kernel 1: tiny 128x128 weight products. grid (128, 2), 128 threads.
// ---------------------------------------------------------------------------
__global__ void prep_MP(const float* __restrict__ Wq, const float* __restrict__ Wk,
                        const float* __restrict__ Wv, const float* __restrict__ W1)
{
    __shared__ float arow[H];
    int r = blockIdx.x;
    int c = threadIdx.x;
    int m = blockIdx.y;
    const float* A = (m == 0) ? Wq : Wv;
    arow[c] = A[r * H + c];
    __syncthreads();

    float acc = 0.0f;
    if (m == 0) {
        const float4* wk4 = (const float4*)(Wk + c * H);
        #pragma unroll 8
        for (int d4 = 0; d4 < H / 4; d4++) {
            float4 w = wk4[d4];
            acc += arow[4 * d4 + 0] * w.x + arow[4 * d4 + 1] * w.y
                 + arow[4 * d4 + 2] * w.z + arow[4 * d4 + 3] * w.w;
        }
        g_M[r * H + c] = acc;
    } else {
        #pragma unroll 8
        for (int d = 0; d < H; d++)
            acc = fmaf(arow[d], W1[(H + d) * H + c], acc);
        g_P[r * H + c] = acc;
    }
}

// ---------------------------------------------------------------------------
// Kernel 2: qk = vs0 @ M   ([2048,128] @ [128,128]). grid 128, 128 threads.
// ---------------------------------------------------------------------------
__global__ void qk_kernel(const float* __restrict__ vs)
{
    __shared__ float Ms[H * H];
    __shared__ float xs[16 * H];
    int c  = threadIdx.x;
    int i0 = blockIdx.x * 16;
    for (int k = 0; k < H; k++) Ms[k * H + c] = g_M[k * H + c];
    for (int r = 0; r < 16; r++) xs[r * H + c] = vs[(i0 + r) * H + c];
    __syncthreads();
    for (int r = 0; r < 16; r++) {
        float acc = 0.0f;
        #pragma unroll 8
        for (int h = 0; h < H; h++)
            acc = fmaf(xs[r * H + h], Ms[h * H + c], acc);
        g_qk[(i0 + r) * H + c] = acc;
    }
}

// ---------------------------------------------------------------------------
// Kernel 3: MAIN. One CTA per (b,a), 256 threads, single pass over ve.
// 8 entities per iteration, double-buffered prefetch (MLP ~8), 9-shfl
// multireduce, online softmax with 2 MUFU/iter.
// ---------------------------------------------------------------------------
__global__ void __launch_bounds__(256, 2)
main_kernel(const float* __restrict__ ve, const int* __restrict__ dead)
{
    __shared__ float scomp[E];        // compat (with -inf dead mask)
    __shared__ float swm[8], sws[8];  // per-warp online max / sum
    __shared__ float sacc[8 * H];     // per-warp weighted accumulators
    __shared__ int   ssel[KF];

    const int i   = blockIdx.x;
    const int tid = threadIdx.x;
    const int w   = tid >> 5;
    const int l   = tid & 31;
    const unsigned FULL = 0xffffffffu;

    const float4* ve4 = (const float4*)(ve + (size_t)i * E * H);
    const float4  qk4 = ((const float4*)(g_qk + (size_t)i * H))[l];

    // dead flags for this warp's 32 entities, one per lane
    const int dl = dead[i * E + w * 32 + l];

    float  m = -INFINITY, s = 0.0f;
    float4 acc = make_float4(0.f, 0.f, 0.f, 0.f);

    float4 buf[2][8];
    {
        const int e0 = w * 32;
        #pragma unroll
        for (int j = 0; j < 8; j++) buf[0][j] = ve4[(e0 + j) * 32 + l];
    }

    #pragma unroll
    for (int g = 0; g < 4; g++) {
        float4* cb = buf[g & 1];
        float4* nb = buf[(g + 1) & 1];
        if (g < 3) {
            const int e0 = w * 32 + (g + 1) * 8;
            #pragma unroll
            for (int j = 0; j < 8; j++) nb[j] = ve4[(e0 + j) * 32 + l];
        }
        const int ebase = w * 32 + g * 8;

        float sj[8];
        #pragma unroll
        for (int j = 0; j < 8; j++)
            sj[j] = cb[j].x * qk4.x + cb[j].y * qk4.y
                  + cb[j].z * qk4.z + cb[j].w * qk4.w;

        // 8-wide multireduce: a = full dot of entity ebase+(l&7), replicated x4
        float a01 = (l & 1) ? sj[1] : sj[0];
        float u01 = (l & 1) ? sj[0] : sj[1];
        a01 += __shfl_xor_sync(FULL, u01, 1);
        float a23 = (l & 1) ? sj[3] : sj[2];
        float u23 = (l & 1) ? sj[2] : sj[3];
        a23 += __shfl_xor_sync(FULL, u23, 1);
        float a45 = (l & 1) ? sj[5] : sj[4];
        float u45 = (l & 1) ? sj[4] : sj[5];
        a45 += __shfl_xor_sync(FULL, u45, 1);
        float a67 = (l & 1) ? sj[7] : sj[6];
        float u67 = (l & 1) ? sj[6] : sj[7];
        a67 += __shfl_xor_sync(FULL, u67, 1);

        float b03 = (l & 2) ? a23 : a01;
        float v03 = (l & 2) ? a01 : a23;
        b03 += __shfl_xor_sync(FULL, v03, 2);
        float b47 = (l & 2) ? a67 : a45;
        float v47 = (l & 2) ? a45 : a67;
        b47 += __shfl_xor_sync(FULL, v47, 2);

        float a  = (l & 4) ? b47 : b03;
        float vx = (l & 4) ? b03 : b47;
        a += __shfl_xor_sync(FULL, vx, 4);
        a += __shfl_xor_sync(FULL, a, 8);
        a += __shfl_xor_sync(FULL, a, 16);

        // dead mask for lane's entity (value lives on lane g*8+(l&7))
        const int dmask = __shfl_sync(FULL, dl, g * 8 + (l & 7));
        float cmp = dmask ? -INFINITY : NORM * a;
        if (l < 8) scomp[ebase + l] = cmp;

        // group max (values replicated over l&7 domain)
        float cm = fmaxf(cmp, __shfl_xor_sync(FULL, cmp, 1));
        cm = fmaxf(cm, __shfl_xor_sync(FULL, cm, 2));
        cm = fmaxf(cm, __shfl_xor_sync(FULL, cm, 4));
        float mn = fmaxf(m, cm);
        if (mn != -INFINITY) {
            float sc = __expf(m - mn);
            float p  = __expf(cmp - mn);
            // sum of the 8 p's
            float ps = p + __shfl_xor_sync(FULL, p, 1);
            ps += __shfl_xor_sync(FULL, ps, 2);
            ps += __shfl_xor_sync(FULL, ps, 4);
            s = fmaf(s, sc, ps);
            // broadcast each p_j
            float pj[8];
            #pragma unroll
            for (int j = 0; j < 8; j++) pj[j] = __shfl_sync(FULL, p, j, 8);
            float sx = 0.f, sy = 0.f, sz = 0.f, sw2 = 0.f;
            #pragma unroll
            for (int j = 0; j < 8; j++) {
                sx  = fmaf(pj[j], cb[j].x, sx);
                sy  = fmaf(pj[j], cb[j].y, sy);
                sz  = fmaf(pj[j], cb[j].z, sz);
                sw2 = fmaf(pj[j], cb[j].w, sw2);
            }
            acc.x = fmaf(acc.x, sc, sx);
            acc.y = fmaf(acc.y, sc, sy);
            acc.z = fmaf(acc.z, sc, sz);
            acc.w = fmaf(acc.w, sc, sw2);
            m = mn;
        }
    }

    if (l == 0) { swm[w] = m; sws[w] = s; }
    ((float4*)sacc)[w * 32 + l] = acc;
    __syncthreads();

    // ---- cross-warp combine -> wve (threads 0..127) ----
    if (tid < H) {
        float M = swm[0];
        #pragma unroll
        for (int j = 1; j < 8; j++) M = fmaxf(M, swm[j]);
        float tot = 0.0f, sum = 0.0f;
        if (M != -INFINITY) {
            #pragma unroll
            for (int j = 0; j < 8; j++) {
                float f = __expf(swm[j] - M);
                tot = fmaf(sws[j], f, tot);
                sum = fmaf(f, sacc[j * H + tid], sum);
            }
        }
        g_wve[(size_t)i * H + tid] = (tot > 0.0f) ? sum / tot : 0.0f;
    }

    // ---- top-12 on compat (warp 0): desc value, asc index ties ----
    if (w == 0) {
        unsigned sel = 0;   // bit j: my entity j*32+l already selected
        for (int k = 0; k < KF; k++) {
            float bv = -INFINITY; int bi = 0x7fffffff;
            #pragma unroll
            for (int j = 0; j < 8; j++) {
                if ((sel >> j) & 1u) continue;
                int e = j * 32 + l;
                float v = scomp[e];
                if (v > bv || (v == bv && e < bi)) { bv = v; bi = e; }
            }
            #pragma unroll
            for (int off = 16; off; off >>= 1) {
                float ov = __shfl_xor_sync(FULL, bv, off);
                int   oi = __shfl_xor_sync(FULL, bi, off);
                if (ov > bv || (ov == bv && oi < bi)) { bv = ov; bi = oi; }
            }
            if ((bi & 31) == l) sel |= 1u << (bi >> 5);
            if (l == 0) ssel[k] = bi;
        }
    }
    __syncthreads();

    // ---- gather selected rows (8 warps, strided over 12) ----
    for (int k = w; k < KF; k += 8) {
        int e = ssel[k];
        ((float4*)g_veC)[((size_t)i * KF + k) * 32 + l] = ve4[e * 32 + l];
    }
}

// ---------------------------------------------------------------------------
// Kernel 4: v_M = relu([vs0|wve] @ [W1a;P] + b1). K=256 in 4 chunks of 64.
// grid 256, 128 threads, 8 rows/block. (R4 version — profiled 14 us)
// ---------------------------------------------------------------------------
#define RBM 8
__global__ void __launch_bounds__(128)
vM_kernel(const float* __restrict__ vs, const float* __restrict__ W1,
          const float* __restrict__ b1, float* __restrict__ out)
{
    __shared__ float sw[64 * H];    // 32 KB
    __shared__ float sx[RBM * 64];
    const int c  = threadIdx.x;
    const int i0 = blockIdx.x * RBM;

    float acc[RBM];
    #pragma unroll
    for (int r = 0; r < RBM; r++) acc[r] = 0.0f;

    #pragma unroll
    for (int ch = 0; ch < 4; ch++) {
        const int j0 = ch * 64;
        const float* wsrc = (j0 < 128) ? (W1 + (size_t)j0 * H)
                                       : (g_P + (size_t)(j0 - 128) * H);
        const float4* w4  = (const float4*)wsrc;
        float4*       sw4 = (float4*)sw;
        #pragma unroll
        for (int t = 0; t < 16; t++) sw4[t * 128 + c] = w4[t * 128 + c];
        {
            int r = c >> 4, q = c & 15;
            const float* src = (j0 < 128)
                ? (vs    + (size_t)(i0 + r) * H + j0 + q * 4)
                : (g_wve + (size_t)(i0 + r) * H + (j0 - 128) + q * 4);
            ((float4*)sx)[c] = *(const float4*)src;
        }
        __syncthreads();
        #pragma unroll 4
        for (int jj = 0; jj < 64; jj++) {
            float wv = sw[jj * H + c];
            #pragma unroll
            for (int r = 0; r < RBM; r++)
                acc[r] = fmaf(sx[r * 64 + jj], wv, acc[r]);
        }
        __syncthreads();
    }
    float bb = b1[c];
    #pragma unroll
    for (int r = 0; r < RBM; r++)
        out[(size_t)BA * H + (size_t)(i0 + r) * H + c] = fmaxf(acc[r] + bb, 0.0f);
}

// ---------------------------------------------------------------------------
// Kernel 5: v_C = relu([vs0 | veC] @ W2 + b2). [2048,1664]@[1664,128].
// 256 blocks x 256 threads, K split in two halves of 26 x 32-row chunks.
// (R4 version)
// ---------------------------------------------------------------------------
#define RBC 8
__global__ void __launch_bounds__(256)
vC_kernel(const float* __restrict__ vs, const float* __restrict__ W2,
          const float* __restrict__ b2, float* __restrict__ out)
{
    __shared__ float sw[2][32 * H];    // 32 KB
    __shared__ float sx[2][RBC * 32];  // 2 KB
    __shared__ float sred[RBC * H];    // 4 KB
    const int tid = threadIdx.x;
    const int hf  = tid >> 7;          // K-half
    const int c   = tid & 127;         // output column
    const int i0  = blockIdx.x * RBC;

    float acc[RBC];
    #pragma unroll
    for (int r = 0; r < RBC; r++) acc[r] = 0.0f;

    for (int ch = 0; ch < 26; ch++) {
        const int j0 = (hf * 26 + ch) * 32;   // global K offset
        const float4* w4  = (const float4*)(W2 + (size_t)j0 * H);
        float4*       sw4 = (float4*)sw[hf];
        #pragma unroll
        for (int t = 0; t < 8; t++) sw4[t * 128 + c] = w4[t * 128 + c];
        if (c < 64) {
            int r = c >> 3, q = c & 7;
            const float* src = (j0 < 128)
                ? (vs    + (size_t)(i0 + r) * H + j0 + q * 4)
                : (g_veC + (size_t)(i0 + r) * KF * H + (j0 - 128) + q * 4);
            ((float4*)sx[hf])[c] = *(const float4*)src;
        }
        __syncthreads();
        #pragma unroll 4
        for (int jj = 0; jj < 32; jj++) {
            float wv = sw[hf][jj * H + c];
            #pragma unroll
            for (int r = 0; r < RBC; r++)
                acc[r] = fmaf(sx[hf][r * 32 + jj], wv, acc[r]);
        }
        __syncthreads();
    }
    if (hf) {
        #pragma unroll
        for (int r = 0; r < RBC; r++) sred[r * H + c] = acc[r];
    }
    __syncthreads();
    if (!hf) {
        float bb = b2[c];
        #pragma unroll
        for (int r = 0; r < RBC; r++)
            out[(size_t)(i0 + r) * H + c] =
                fmaxf(acc[r] + sred[r * H + c] + bb, 0.0f);
    }
}

// ---------------------------------------------------------------------------
extern "C" void kernel_launch(void* const* d_in, const int* in_sizes, int n_in,
                              void* d_out, int out_size)
{
    const float* vs   = (const float*)d_in[0];
    const float* ve   = (const float*)d_in[1];
    const int*   dead = (const int*)  d_in[2];
    const float* Wq   = (const float*)d_in[3];
    const float* Wk   = (const float*)d_in[4];
    const float* Wv   = (const float*)d_in[5];
    const float* W1   = (const float*)d_in[6];
    const float* b1   = (const float*)d_in[7];
    const float* W2   = (const float*)d_in[8];
    const float* b2   = (const float*)d_in[9];
    float* out = (float*)d_out;

    prep_MP   <<<dim3(128, 2), 128>>>(Wq, Wk, Wv, W1);
    qk_kernel <<<128, 128>>>(vs);
    main_kernel<<<BA, 256>>>(ve, dead);
    vM_kernel <<<BA / RBM, 128>>>(vs, W1, b1, out);
    vC_kernel <<<BA / RBC, 256>>>(vs, W2, b2, out);
}